// round 17
// baseline (speedup 1.0000x reference)
#include <cuda_runtime.h>
#include <cuda_fp16.h>
#include <math.h>
#include <stdint.h>

#define B_  2
#define T_  2048
#define D_  2048
#define NH_ 16
#define KH_ 4
#define H_  128

__device__ __half g_xqh [B_*T_*D_];
__device__ __half g_xkvh[B_*T_*D_];
__device__ __half g_wqt [NH_*H_*D_];
__device__ __half g_wkt [KH_*H_*D_];
__device__ __half g_wvt [KH_*H_*D_];
__device__ __half g_wot [D_*NH_*H_];
__device__ float2 g_scq [B_*T_*64];
__device__ float2 g_sck [B_*T_*64];
__device__ __half g_qh [B_*T_*NH_*H_];
__device__ __half g_kh [B_*T_*KH_*H_];
__device__ __half g_vt [B_*KH_*H_*T_];
__device__ __half g_attn[B_*T_*NH_*H_];

__device__ __forceinline__ uint32_t f2h2(float lo, float hi) {
    __half2 h = __floats2half2_rn(lo, hi);
    return *(uint32_t*)&h;
}

__device__ __forceinline__ float ex2f(float x) {
    float r;
    asm("ex2.approx.f32 %0, %1;" : "=f"(r) : "f"(x));
    return r;
}

__device__ __forceinline__ void cpasync16(void* dst, const void* src) {
    uint32_t d = (uint32_t)__cvta_generic_to_shared(dst);
    asm volatile("cp.async.cg.shared.global [%0], [%1], 16;\n" :: "r"(d), "l"(src));
}

__device__ __forceinline__ uint32_t smem_u32(const void* p) {
    return (uint32_t)__cvta_generic_to_shared(p);
}

__device__ __forceinline__ void mma16(float* c, const uint32_t* a, const uint32_t* b) {
    asm volatile(
        "mma.sync.aligned.m16n8k16.row.col.f32.f16.f16.f32 "
        "{%0,%1,%2,%3}, {%4,%5,%6,%7}, {%8,%9}, {%0,%1,%2,%3};\n"
        : "+f"(c[0]), "+f"(c[1]), "+f"(c[2]), "+f"(c[3])
        : "r"(a[0]), "r"(a[1]), "r"(a[2]), "r"(a[3]),
          "r"(b[0]), "r"(b[1]));
}

__device__ __forceinline__ void ldsm4(uint32_t& r0, uint32_t& r1,
                                      uint32_t& r2, uint32_t& r3, uint32_t addr) {
    asm volatile("ldmatrix.sync.aligned.m8n8.x4.shared.b16 {%0,%1,%2,%3}, [%4];"
                 : "=r"(r0), "=r"(r1), "=r"(r2), "=r"(r3) : "r"(addr));
}

// ---------------------------------------------------------------------------
// PREP (unchanged)
// ---------------------------------------------------------------------------
#define NCVT  ((B_*T_*D_) / 1024)
#define TQ_   ((NH_*H_/32) * (D_/32))
#define TK_   ((KH_*H_/32) * (D_/32))
#define TO_   ((D_/32) * (NH_*H_/32))
#define NROPE ((B_*T_) / 4)
#define PREP_GRID (2*NCVT + TQ_ + 2*TK_ + TO_ + NROPE)

__device__ __forceinline__
void tr_tile(const float* __restrict__ src, __half* __restrict__ dst,
             int R, int C, int c0, int r0, float (*tile)[33]) {
    int tx = threadIdx.x & 31, ty = threadIdx.x >> 5;
#pragma unroll
    for (int i = 0; i < 32; i += 8)
        tile[ty + i][tx] = src[(size_t)(r0 + ty + i) * C + c0 + tx];
    __syncthreads();
#pragma unroll
    for (int i = 0; i < 32; i += 8)
        dst[(size_t)(c0 + ty + i) * R + r0 + tx] = __float2half_rn(tile[tx][ty + i]);
}

__global__ void prep(const float* __restrict__ Xq, const float* __restrict__ Xkv,
                     __half2* __restrict__ xqh, __half2* __restrict__ xkvh,
                     const float* __restrict__ Wq, const float* __restrict__ Wk,
                     const float* __restrict__ Wv, const float* __restrict__ Wo,
                     __half* __restrict__ wqt, __half* __restrict__ wkt,
                     __half* __restrict__ wvt, __half* __restrict__ wot,
                     const int* __restrict__ qpos, const int* __restrict__ kpos,
                     float2* __restrict__ scq, float2* __restrict__ sck) {
    __shared__ float tile[32][33];
    int bid = blockIdx.x, tid = threadIdx.x;

    if (bid < 2 * NCVT) {
        const float* s = (bid < NCVT) ? Xq : Xkv;
        __half2* d = (bid < NCVT) ? xqh : xkvh;
        int i = (bid % NCVT) * 256 + tid;
        float4 a = ((const float4*)s)[i];
        d[2*i]   = __floats2half2_rn(a.x, a.y);
        d[2*i+1] = __floats2half2_rn(a.z, a.w);
        return;
    }
    bid -= 2 * NCVT;
    if (bid < TQ_) {
        int nx = NH_ * H_ / 32;
        tr_tile(Wq, wqt, D_, NH_*H_, (bid % nx) * 32, (bid / nx) * 32, tile);
        return;
    }
    bid -= TQ_;
    if (bid < 2 * TK_) {
        const float* s = (bid < TK_) ? Wk : Wv;
        __half* d = (bid < TK_) ? wkt : wvt;
        int r = bid % TK_, nx = KH_ * H_ / 32;
        tr_tile(s, d, D_, KH_*H_, (r % nx) * 32, (r / nx) * 32, tile);
        return;
    }
    bid -= 2 * TK_;
    if (bid < TO_) {
        int nx = D_ / 32;
        tr_tile(Wo, wot, NH_*H_, D_, (bid % nx) * 32, (bid / nx) * 32, tile);
        return;
    }
    bid -= TO_;
    {
        int token = bid * 4 + (tid >> 6);
        int i = tid & 63;
        double ts = exp(((double)i / 64.0) * 9.210340371976182736);
        double s_, c_;
        float angq = (float)qpos[token] / (float)ts;
        sincos((double)angq, &s_, &c_);
        scq[token * 64 + i] = make_float2((float)s_, (float)c_);
        float angk = (float)kpos[token] / (float)ts;
        sincos((double)angk, &s_, &c_);
        sck[token * 64 + i] = make_float2((float)s_, (float)c_);
    }
}

// ---------------------------------------------------------------------------
// Shared fp16 GEMM mainloop (R16, unchanged): ldmatrix + single sync
// ---------------------------------------------------------------------------
#define GST 20
#define CST 133

__device__ __forceinline__
void gemm_mainloop(const uint32_t* __restrict__ A, const uint32_t* __restrict__ Bt,
                   int Kd, uint32_t* pool, float acc[4][4][4],
                   int brow, int bcol) {
    uint32_t* As = pool;
    uint32_t* Bs = pool + 5120;
    int tid  = threadIdx.x;
    int warp = tid >> 5, lane = tid & 31;
    int mw = (warp >> 2) * 64, nw = (warp & 3) * 32;

    int l16 = lane & 15, lh = lane >> 4;
    int rowsel = ((lane >> 4) & 1) * 8 + (lane & 7);
    int offw   = ((lane >> 3) & 1) * 4;

#pragma unroll
    for (int mi = 0; mi < 4; mi++)
#pragma unroll
        for (int ni = 0; ni < 4; ni++)
#pragma unroll
            for (int j = 0; j < 4; j++) acc[mi][ni][j] = 0.f;

    const int nkt = Kd >> 5;
    int KW = Kd >> 1;

    auto load_stage = [&](int kt, int buf) {
        int kw0 = kt * 16;
#pragma unroll
        for (int u = 0; u < 2; u++) {
            int c = tid + 256 * u;
            int row = c >> 2, w4 = (c & 3) * 4;
            cpasync16(&As[buf * 2560 + row * GST + w4],
                      &A[(size_t)(brow + row) * KW + kw0 + w4]);
            cpasync16(&Bs[buf * 2560 + row * GST + w4],
                      &Bt[(size_t)(bcol + row) * KW + kw0 + w4]);
        }
        asm volatile("cp.async.commit_group;\n");
    };

    uint32_t as_base = smem_u32(As);
    uint32_t bs_base = smem_u32(Bs);

    load_stage(0, 0);

    for (int kt = 0; kt < nkt; kt++) {
        int buf = kt & 1;
        asm volatile("cp.async.wait_group 0;\n");
        __syncthreads();
        if (kt + 1 < nkt) load_stage(kt + 1, buf ^ 1);

        uint32_t ab = as_base + (uint32_t)(buf * 2560 + (mw + l16) * GST + lh * 4) * 4;
        uint32_t bb = bs_base + (uint32_t)(buf * 2560 + (nw + rowsel) * GST + offw) * 4;

#pragma unroll
        for (int ks = 0; ks < 2; ks++) {
            uint32_t af[4][4], bf2[2][4];
#pragma unroll
            for (int mi = 0; mi < 4; mi++)
                ldsm4(af[mi][0], af[mi][1], af[mi][2], af[mi][3],
                      ab + (uint32_t)(mi * 16 * GST + ks * 8) * 4);
#pragma unroll
            for (int p = 0; p < 2; p++)
                ldsm4(bf2[p][0], bf2[p][1], bf2[p][2], bf2[p][3],
                      bb + (uint32_t)(p * 16 * GST + ks * 8) * 4);
#pragma unroll
            for (int mi = 0; mi < 4; mi++) {
#pragma unroll
                for (int ni = 0; ni < 4; ni++) {
                    const uint32_t* bfp = &bf2[ni >> 1][(ni & 1) * 2];
                    mma16(acc[mi][ni], af[mi], bfp);
                }
            }
        }
    }
    __syncthreads();
}

__device__ __forceinline__
void stage_pass(float* Cs, float acc[4][4][4], int p) {
    int tid = threadIdx.x, warp = tid >> 5, lane = tid & 31;
    int nw = (warp & 3) * 32;
    int lr = lane >> 2, lc = lane & 3;
    if ((warp >> 2) == p) {
#pragma unroll
        for (int mi = 0; mi < 4; mi++) {
#pragma unroll
            for (int ni = 0; ni < 4; ni++) {
                int r0 = mi * 16 + lr, cc = nw + ni * 8 + 2 * lc;
                Cs[r0 * CST + cc]           = acc[mi][ni][0];
                Cs[r0 * CST + cc + 1]       = acc[mi][ni][1];
                Cs[(r0 + 8) * CST + cc]     = acc[mi][ni][2];
                Cs[(r0 + 8) * CST + cc + 1] = acc[mi][ni][3];
            }
        }
    }
}

// ---------------------------------------------------------------------------
// PROJ_ALL (unchanged)
// ---------------------------------------------------------------------------
__global__ __launch_bounds__(256, 2)
void proj_all(const uint32_t* __restrict__ xqh, const uint32_t* __restrict__ xkvh,
              const uint32_t* __restrict__ wqt, const uint32_t* __restrict__ wkt,
              const uint32_t* __restrict__ wvt,
              __half* __restrict__ qdst, __half* __restrict__ kdst,
              __half* __restrict__ vdst,
              const float2* __restrict__ scq, const float2* __restrict__ sck,
              float scale) {
    __shared__ uint32_t pool[10240];
    float acc[4][4][4];
    int bid = blockIdx.x, tid = threadIdx.x;
    float* Cs = (float*)pool;

    if (bid < 512) {
        int n = bid & 15, brow = (bid >> 4) * 128;
        gemm_mainloop(xqh, wqt, D_, pool, acc, brow, n * 128);
#pragma unroll
        for (int p = 0; p < 2; p++) {
            stage_pass(Cs, acc, p);
            __syncthreads();
            int row = tid >> 2, g = tid & 3;
            int token = brow + p * 64 + row;
            const float2* scrow = scq + (size_t)token * 64;
            __half* drow = qdst + (((size_t)token * NH_ + n) << 7);
#pragma unroll
            for (int j = 0; j < 16; j++) {
                int i = g * 16 + j;
                float2 scv = scrow[i];
                float x1 = Cs[row * CST + i];
                float x2 = Cs[row * CST + i + 64];
                drow[i]      = __float2half_rn((x1 * scv.y - x2 * scv.x) * scale);
                drow[i + 64] = __float2half_rn((x2 * scv.y + x1 * scv.x) * scale);
            }
            __syncthreads();
        }
    } else if (bid < 640) {
        int r = bid - 512;
        int kh = r & 3, brow = (r >> 2) * 128;
        gemm_mainloop(xkvh, wkt, D_, pool, acc, brow, kh * 128);
#pragma unroll
        for (int p = 0; p < 2; p++) {
            stage_pass(Cs, acc, p);
            __syncthreads();
            int row = tid >> 2, g = tid & 3;
            int token = brow + p * 64 + row;
            const float2* scrow = sck + (size_t)token * 64;
            __half* drow = kdst + (((size_t)token * KH_ + kh) << 7);
#pragma unroll
            for (int j = 0; j < 16; j++) {
                int i = g * 16 + j;
                float2 scv = scrow[i];
                float x1 = Cs[row * CST + i];
                float x2 = Cs[row * CST + i + 64];
                drow[i]      = __float2half_rn(x1 * scv.y - x2 * scv.x);
                drow[i + 64] = __float2half_rn(x2 * scv.y + x1 * scv.x);
            }
            __syncthreads();
        }
    } else {
        int r = bid - 640;
        int kh = r & 3, brow = (r >> 2) * 128;
        gemm_mainloop(xkvh, wvt, D_, pool, acc, brow, kh * 128);
#pragma unroll
        for (int p = 0; p < 2; p++) {
            stage_pass(Cs, acc, p);
            __syncthreads();
            int h = tid >> 1, half = tid & 1;
            int tglob = brow + p * 64 + half * 32;
            int b = tglob / T_, tloc = tglob % T_;
            __half* dstp = vdst + ((size_t)(b * KH_ + kh) * H_ + h) * T_ + tloc;
#pragma unroll
            for (int j = 0; j < 32; j++)
                dstp[j] = __float2half_rn(Cs[(half * 32 + j) * CST + h]);
            __syncthreads();
        }
    }
}

// ---------------------------------------------------------------------------
// Plain GEMM (output projection, unchanged)
// ---------------------------------------------------------------------------
__global__ __launch_bounds__(256, 2)
void gemm16(const uint32_t* __restrict__ A, const uint32_t* __restrict__ Bt,
            float* __restrict__ C, int Nc, int Kd) {
    __shared__ uint32_t pool[10240];
    float acc[4][4][4];
    int brow = blockIdx.y * 128, bcol = blockIdx.x * 128;
    gemm_mainloop(A, Bt, Kd, pool, acc, brow, bcol);

    int tid = threadIdx.x, warp = tid >> 5, lane = tid & 31;
    int mw = (warp >> 2) * 64, nw = (warp & 3) * 32;
    int lr = lane >> 2, lc = lane & 3;
#pragma unroll
    for (int mi = 0; mi < 4; mi++) {
#pragma unroll
        for (int ni = 0; ni < 4; ni++) {
            int r0 = brow + mw + mi * 16 + lr;
            int cc = bcol + nw + ni * 8 + lc * 2;
            *(float2*)&C[(size_t)r0 * Nc + cc] =
                make_float2(acc[mi][ni][0], acc[mi][ni][1]);
            *(float2*)&C[(size_t)(r0 + 8) * Nc + cc] =
                make_float2(acc[mi][ni][2], acc[mi][ni][3]);
        }
    }
}

// ---------------------------------------------------------------------------
// FP16 flash attention — 2 blocks/SM: Q resident in smem, KV tile 64,
// P in registers (C-frag -> A-frag pack), ldmatrix everywhere, 1 sync/tile.
// smem: Qs 128x68 + Ks 2x64x68 + Vs 2x128x36 = 104KB.
// ---------------------------------------------------------------------------
#define QST 68
#define KST 68
#define VSTW 36
#define FA_SMEM ((128*QST + 2*64*KST + 2*128*VSTW) * 4)

__global__ __launch_bounds__(256, 2)
void flash16(const uint32_t* __restrict__ qh, const uint32_t* __restrict__ kk,
             const uint32_t* __restrict__ vt, uint32_t* __restrict__ o) {
    extern __shared__ uint32_t sm_u[];
    uint32_t* Qs = sm_u;                  // [128][QST]
    uint32_t* Ks = Qs + 128 * QST;        // [2][64*KST]
    uint32_t* Vs = Ks + 2 * 64 * KST;     // [2][128*VSTW]

    int qt = (int)gridDim.x - 1 - (int)blockIdx.x;
    int n  = blockIdx.y;
    int b  = blockIdx.z;
    int khd = n >> 2;
    int tid = threadIdx.x, warp = tid >> 5, lane = tid & 31;
    int lr = lane >> 2, lc = lane & 3;
    int q0 = qt * 128;

    int l16 = lane & 15, lh = lane >> 4;
    int rowsel = ((lane >> 4) & 1) * 8 + (lane & 7);
    int offw   = ((lane >> 3) & 1) * 4;

    // ---- load Q tile (resident) ----
#pragma unroll
    for (int u = 0; u < 8; u++) {
        int f = tid + 256 * u;
        int r = f >> 4, w4 = (f & 15) * 4;
        *(uint4*)(Qs + r * QST + w4) = *(const uint4*)(qh +
            ((size_t)((b * T_ + q0 + r) * NH_ + n) << 6) + w4);
    }

    float m_[2] = {-1e30f, -1e30f};
    float l_[2] = {0.f, 0.f};
    float oacc[16][4];
#pragma unroll
    for (int ns = 0; ns < 16; ns++)
#pragma unroll
        for (int j = 0; j < 4; j++) oacc[ns][j] = 0.f;

    int row0 = q0 + warp * 16 + lr;
    int njt = 2 * qt + 2;
    uint32_t qbase = smem_u32(Qs) + (uint32_t)((warp * 16 + l16) * QST + lh * 4) * 4;

    auto load_kv = [&](int jt, int bufsel) {
        int s0 = jt * 64;
        uint32_t* Kd = Ks + bufsel * 64 * KST;
        uint32_t* Vd = Vs + bufsel * 128 * VSTW;
#pragma unroll
        for (int u = 0; u < 4; u++) {
            int f = tid + 256 * u;
            int r = f >> 4, w4 = (f & 15) * 4;          // K: 64 rows x 16 chunks
            cpasync16(Kd + r * KST + w4,
                      kk + ((size_t)((b * T_ + s0 + r) * KH_ + khd) << 6) + w4);
            int hr = f >> 3, vw4 = (f & 7) * 4;         // V^T: 128 rows x 8 chunks
            cpasync16(Vd + hr * VSTW + vw4,
                      vt + ((((size_t)(b * KH_ + khd) * H_ + hr) * T_ + s0) >> 1) + vw4);
        }
        asm volatile("cp.async.commit_group;\n");
    };

    load_kv(0, 0);

    for (int jt = 0; jt < njt; jt++) {
        int buf = jt & 1;
        asm volatile("cp.async.wait_group 0;\n");
        __syncthreads();
        if (jt + 1 < njt) load_kv(jt + 1, buf ^ 1);

        uint32_t kb0 = smem_u32(Ks) + (uint32_t)(buf * 64 * KST) * 4
                     + (uint32_t)(rowsel * KST + offw) * 4;
        uint32_t vb0 = smem_u32(Vs) + (uint32_t)(buf * 128 * VSTW) * 4
                     + (uint32_t)(rowsel * VSTW + offw) * 4;
        int s0 = jt * 64;

        // ---- S = Q K^T ----
        float s_[8][4];
#pragma unroll
        for (int ns = 0; ns < 8; ns++)
#pragma unroll
            for (int j = 0; j < 4; j++) s_[ns][j] = 0.f;
#pragma unroll
        for (int hs = 0; hs < 8; hs++) {
            uint32_t qf[4];
            ldsm4(qf[0], qf[1], qf[2], qf[3], qbase + (uint32_t)(hs * 8) * 4);
#pragma unroll
            for (int np = 0; np < 4; np++) {
                uint32_t b0, b1, b2, b3;
                ldsm4(b0, b1, b2, b3,
                      kb0 + (uint32_t)(np * 16 * KST + hs * 8) * 4);
                uint32_t bfa[2] = {b0, b1}, bfb[2] = {b2, b3};
                mma16(s_[2 * np],     qf, bfa);
                mma16(s_[2 * np + 1], qf, bfb);
            }
        }

        // ---- causal mask (last two kv tiles cross the diagonal) ----
        if (jt >= 2 * qt) {
#pragma unroll
            for (int ns = 0; ns < 8; ns++) {
                int col = s0 + ns * 8 + 2 * lc;
                if (col > row0)     s_[ns][0] = -1e30f;
                if (col + 1 > row0) s_[ns][1] = -1e30f;
                if (col > row0 + 8)     s_[ns][2] = -1e30f;
                if (col + 1 > row0 + 8) s_[ns][3] = -1e30f;
            }
        }

        // ---- online softmax (base-2); P packed in place into s_ ----
        float mx0 = -1e30f, mx1 = -1e30f;
#pragma unroll
        for (int ns = 0; ns < 8; ns++) {
            mx0 = fmaxf(mx0, fmaxf(s_[ns][0], s_[ns][1]));
            mx1 = fmaxf(mx1, fmaxf(s_[ns][2], s_[ns][3]));
        }
        mx0 = fmaxf(mx0, __shfl_xor_sync(0xffffffffu, mx0, 1));
        mx0 = fmaxf(mx0, __shfl_xor_sync(0xffffffffu, mx0, 2));
        mx1 = fmaxf(mx1, __shfl_xor_sync(0xffffffffu, mx1, 1));
        mx1 = fmaxf(mx1, __shfl_xor_sync(0xffffffffu, mx1, 2));
        float mn0 = fmaxf(m_[0], mx0), mn1 = fmaxf(m_[1], mx1);
        float a0 = ex2f(m_[0] - mn0), a1 = ex2f(m_[1] - mn1);
        float sum0 = 0.f, sum1 = 0.f;
#pragma unroll
        for (int ns = 0; ns < 8; ns++) {
            float p0 = ex2f(s_[ns][0] - mn0);
            float p1 = ex2f(s_[ns][1] - mn0);
            float p2 = ex2f(s_[ns][2] - mn1);
            float p3 = ex2f(s_[ns][3] - mn1);
            sum0 += p0 + p1;
            sum1 += p2 + p3;
            s_[ns][0] = __uint_as_float(f2h2(p0, p1));  // rows lr   -> a0/a2
            s_[ns][1] = __uint_as_float(f2h2(p2, p3));  // rows lr+8 -> a1/a3
        }
        sum0 += __shfl_xor_sync(0xffffffffu, sum0, 1);
        sum0 += __shfl_xor_sync(0xffffffffu, sum0, 2);
        sum1 += __shfl_xor_sync(0xffffffffu, sum1, 1);
        sum1 += __shfl_xor_sync(0xffffffffu, sum1, 2);
        l_[0] = l_[0] * a0 + sum0;
        l_[1] = l_[1] * a1 + sum1;
        m_[0] = mn0; m_[1] = mn1;

#pragma unroll
        for (int ns = 0; ns < 16; ns++) {
            oacc[ns][0] *= a0; oacc[ns][1] *= a0;
            oacc[ns][2] *= a1; oacc[ns][3] *= a1;
        }

        // ---- O += P V (P from regs, V B-frags via ldmatrix) ----
#pragma unroll
        for (int ks = 0; ks < 4; ks++) {
            uint32_t af[4] = {__float_as_uint(s_[2 * ks][0]),
                              __float_as_uint(s_[2 * ks][1]),
                              __float_as_uint(s_[2 * ks + 1][0]),
                              __float_as_uint(s_[2 * ks + 1][1])};
#pragma unroll
            for (int np = 0; np < 8; np++) {
                uint32_t v0, v1, v2, v3;
                ldsm4(v0, v1, v2, v3,
                      vb0 + (uint32_t)(np * 16 * VSTW + ks * 8) * 4);
                uint32_t bfa[2] = {v0, v1}, bfb[2] = {v2, v3};
                mma16(oacc[2 * np],     af, bfa);
                mma16(oacc[2 * np + 1], af, bfb);
            }
        }
    }

    // ---- epilogue ----
    float inv0 = 1.f / l_[0], inv1 = 1.f / l_[1];
    size_t wb0 = ((size_t)((b * T_ + row0) * NH_ + n) << 6);
    size_t wb1 = ((size_t)((b * T_ + row0 + 8) * NH_ + n) << 6);
#pragma unroll
    for (int ns = 0; ns < 16; ns++) {
        o[wb0 + ns * 4 + lc] = f2h2(oacc[ns][0] * inv0, oacc[ns][1] * inv0);
        o[wb1 + ns * 4 + lc] = f2h2(oacc[ns][2] * inv1, oacc[ns][3] * inv1);
    }
}

// ---------------------------------------------------------------------------
extern "C" void kernel_launch(void* const* d_in, const int* in_sizes, int n_in,
                              void* d_out, int out_size) {
    const float* Xq   = (const float*)d_in[0];
    const float* Xkv  = (const float*)d_in[1];
    const int*   qpos = (const int*)  d_in[2];
    const int*   kpos = (const int*)  d_in[3];
    const float* Wq   = (const float*)d_in[4];
    const float* Wk   = (const float*)d_in[5];
    const float* Wv   = (const float*)d_in[6];
    const float* Wo   = (const float*)d_in[7];
    float* out = (float*)d_out;

    __half *xqh, *xkvh, *wqt, *wkt, *wvt, *wot, *qh, *kh, *vt, *attn;
    float2 *scq, *sck;
    cudaGetSymbolAddress((void**)&xqh,  g_xqh);
    cudaGetSymbolAddress((void**)&xkvh, g_xkvh);
    cudaGetSymbolAddress((void**)&wqt,  g_wqt);
    cudaGetSymbolAddress((void**)&wkt,  g_wkt);
    cudaGetSymbolAddress((void**)&wvt,  g_wvt);
    cudaGetSymbolAddress((void**)&wot,  g_wot);
    cudaGetSymbolAddress((void**)&scq,  g_scq);
    cudaGetSymbolAddress((void**)&sck,  g_sck);
    cudaGetSymbolAddress((void**)&qh,   g_qh);
    cudaGetSymbolAddress((void**)&kh,   g_kh);
    cudaGetSymbolAddress((void**)&vt,   g_vt);
    cudaGetSymbolAddress((void**)&attn, g_attn);

    const int M = B_ * T_;
    const int NHH = NH_ * H_;
    const float scale = 0.08838834764831845f * 1.4426950408889634f;

    prep<<<PREP_GRID, 256>>>(Xq, Xkv, (__half2*)xqh, (__half2*)xkvh,
                             Wq, Wk, Wv, Wo, wqt, wkt, wvt, wot,
                             qpos, kpos, scq, sck);

    proj_all<<<768, 256>>>(
        (const uint32_t*)xqh, (const uint32_t*)xkvh,
        (const uint32_t*)wqt, (const uint32_t*)wkt, (const uint32_t*)wvt,
        qh, kh, vt, scq, sck, scale);

    cudaFuncSetAttribute(flash16,
                         cudaFuncAttributeMaxDynamicSharedMemorySize, FA_SMEM);
    flash16<<<dim3(T_ / 128, NH_, B_), 256, FA_SMEM>>>(
        (const uint32_t*)qh, (const uint32_t*)kh, (const uint32_t*)vt,
        (uint32_t*)attn);

    gemm16<<<dim3(D_ / 128, M / 128), 256>>>(
        (const uint32_t*)attn, (const uint32_t*)wot, out, D_, NHH);
}